// round 13
// baseline (speedup 1.0000x reference)
#include <cuda_runtime.h>
#include <cuda_fp16.h>
#include <cstdint>
#include <math.h>

#define HW 4096
#define NPIX 65536
#define E 256
#define RR 365
#define N1 23920640u

// Scratch (device globals; no runtime allocation allowed)
__device__ __align__(16) __half g_emb_h[NPIX * E];     // UNNORMALIZED conv out (fp16)
__device__ __align__(16) __half g_brep_h[3 * RR * E];  // [m][r][E] fp16 unit reps
__device__ __align__(16) __half g_convw_h[E * E];      // conv_w fp16 [e][cin]
__device__ float g_psum[NPIX];                         // per-pixel sum of probs over r
__device__ float g_ssq[NPIX];                          // per-pixel ||conv out||^2
__device__ float g_inv[NPIX];                          // 1/max(sqrt(ssq),eps)

// ---------------------------------------------------------------------------
// PTX helpers (sm_80+ baseline ISA; compiles for plain sm_103)
// ---------------------------------------------------------------------------
__device__ __forceinline__ uint32_t smem_u32(const void* p) {
    uint32_t a;
    asm("{ .reg .u64 t; cvta.to.shared.u64 t, %1; cvt.u32.u64 %0, t; }"
        : "=r"(a) : "l"(p));
    return a;
}

__device__ __forceinline__ void cp16(uint32_t dst, const void* src, uint32_t sz) {
    asm volatile("cp.async.cg.shared.global [%0], [%1], 16, %2;"
                 :: "r"(dst), "l"(src), "r"(sz));
}
#define CP_COMMIT() asm volatile("cp.async.commit_group;" ::: "memory")
#define CP_WAIT1()  asm volatile("cp.async.wait_group 1;" ::: "memory")
#define CP_WAIT2()  asm volatile("cp.async.wait_group 2;" ::: "memory")

__device__ __forceinline__ void ldsm4(uint32_t r[4], uint32_t addr) {
    asm volatile("ldmatrix.sync.aligned.m8n8.x4.shared.b16 {%0,%1,%2,%3}, [%4];"
                 : "=r"(r[0]), "=r"(r[1]), "=r"(r[2]), "=r"(r[3]) : "r"(addr));
}

// fp16 MMA, fp32 accumulate
__device__ __forceinline__ void mma_f16(float c[4],
                                        uint32_t a0, uint32_t a1, uint32_t a2, uint32_t a3,
                                        uint32_t b0, uint32_t b1) {
    asm volatile(
        "mma.sync.aligned.m16n8k16.row.col.f32.f16.f16.f32 "
        "{%0,%1,%2,%3}, {%4,%5,%6,%7}, {%8,%9}, {%0,%1,%2,%3};"
        : "+f"(c[0]), "+f"(c[1]), "+f"(c[2]), "+f"(c[3])
        : "r"(a0), "r"(a1), "r"(a2), "r"(a3), "r"(b0), "r"(b1));
}

// ---------------------------------------------------------------------------
// Kernel 0: convert conv_w + reps to fp16; zero psum/ssq
// ---------------------------------------------------------------------------
#define NCONV (E * E)
#define NREPS (RR * E)
__global__ void convert_inputs(const float* __restrict__ conv_w,
                               const float* __restrict__ reps) {
    int i = blockIdx.x * 256 + threadIdx.x;
    if (i < NCONV) g_convw_h[i] = __float2half(conv_w[i]);
    else if (i < NCONV + NREPS) g_brep_h[i - NCONV] = __float2half(reps[i - NCONV]);
    if (i < NPIX) { g_psum[i] = 0.f; g_ssq[i] = 0.f; }
}

// ---------------------------------------------------------------------------
// Kernel 1: negative representations -> g_brep_h rows RR..3RR-1 (fp16)
// ---------------------------------------------------------------------------
__global__ __launch_bounds__(256)
void negreps_kernel(const float* __restrict__ reps,
                    const float* __restrict__ neg_w,
                    const float* __restrict__ neg_b) {
    __shared__ __align__(16) float rs[E];
    __shared__ __align__(16) float Ws[16][E];
    __shared__ float red[256];
    int r = blockIdx.x, m = blockIdx.y;
    int t = threadIdx.x;

    rs[t] = reps[r * E + t];
    float off = neg_b[m * E + t];
    const float* wrow = neg_w + (size_t)(m * E + t) * E;

    for (int c0 = 0; c0 < E; c0 += 16) {
        __syncthreads();
        float4 v0 = *(const float4*)(wrow + c0);
        float4 v1 = *(const float4*)(wrow + c0 + 4);
        float4 v2 = *(const float4*)(wrow + c0 + 8);
        float4 v3 = *(const float4*)(wrow + c0 + 12);
        Ws[0][t]  = v0.x; Ws[1][t]  = v0.y; Ws[2][t]  = v0.z; Ws[3][t]  = v0.w;
        Ws[4][t]  = v1.x; Ws[5][t]  = v1.y; Ws[6][t]  = v1.z; Ws[7][t]  = v1.w;
        Ws[8][t]  = v2.x; Ws[9][t]  = v2.y; Ws[10][t] = v2.z; Ws[11][t] = v2.w;
        Ws[12][t] = v3.x; Ws[13][t] = v3.y; Ws[14][t] = v3.z; Ws[15][t] = v3.w;
        __syncthreads();
#pragma unroll
        for (int k = 0; k < 16; k++)
            off = fmaf(fabsf(rs[c0 + k]), Ws[k][t], off);
    }

    float xv = rs[t];
    float sg = (xv > 0.f) ? 1.f : ((xv < 0.f) ? -1.f : 0.f);
    float val = (off + fabsf(xv)) * sg;

    red[t] = val * val;
    __syncthreads();
    for (int s = 128; s > 0; s >>= 1) {
        if (t < s) red[t] += red[t + s];
        __syncthreads();
    }
    float invn = 1.f / fmaxf(sqrtf(red[0]), 1e-12f);
    g_brep_h[(size_t)((m + 1) * RR + r) * E + t] = __float2half(val * invn);
}

// ===========================================================================
// Kernel 2: conv1x1(x)+b, UNNORMALIZED, fp16 out; ssq accumulated globally.
// Block = 64 pix x 128 e (grid.y=2 e-halves). K=256, 8 chunks of k=32,
// 3-stage pipeline, fill distance 2, SINGLE sync per chunk.
// smem: bias[128]@0, ssq_sh[64]@512B, tiles@1024B: stage 15360B x3
// ===========================================================================
#define EMBH_STAGE 15360
#define EMBH_SMEM  (1024 + 3 * EMBH_STAGE)   // 47104

__global__ __launch_bounds__(256, 3)
void emb_f16(const float* __restrict__ x, const float* __restrict__ conv_b) {
    extern __shared__ float smem[];
    float* bias_sh = smem;          // 128
    float* ssq_sh  = smem + 128;    // 64
    uint32_t sb = smem_u32(smem);
    int t = threadIdx.x, lane = t & 31, w = t >> 5;
    int wp = w & 1, wc = w >> 1;    // 32-pix half, 32-e quarter
    int pix0 = blockIdx.x * 64;
    int e0 = blockIdx.y * 128;
    int b = pix0 >> 12, hw0 = pix0 & 4095;

    if (t < 128) bias_sh[t] = conv_b[e0 + t];
    if (t < 64) ssq_sh[t] = 0.f;
    __syncthreads();

    float c[2][4][4];
#pragma unroll
    for (int mt = 0; mt < 2; mt++)
#pragma unroll
        for (int nt = 0; nt < 4; nt++)
#pragma unroll
            for (int q = 0; q < 4; q++) c[mt][nt][q] = 0.f;

    int pixl = t & 63, kq = t >> 6;     // kq: 0..3 (8 k each)
    const float* asrc = x + (size_t)b * E * HW + hw0 + pixl;

    // prologue: stages 0,1 (LDG->STS for A, cp.async for B)
#pragma unroll
    for (int s = 0; s < 2; s++) {
        float v[8];
#pragma unroll
        for (int j = 0; j < 8; j++) v[j] = asrc[(size_t)(s * 32 + kq * 8 + j) * HW];
        __half2 h0 = __floats2half2_rn(v[0], v[1]);
        __half2 h1 = __floats2half2_rn(v[2], v[3]);
        __half2 h2 = __floats2half2_rn(v[4], v[5]);
        __half2 h3 = __floats2half2_rn(v[6], v[7]);
        uint4 pk;
        pk.x = *(const uint32_t*)&h0; pk.y = *(const uint32_t*)&h1;
        pk.z = *(const uint32_t*)&h2; pk.w = *(const uint32_t*)&h3;
        *(uint4*)((char*)smem + 1024 + s * EMBH_STAGE + pixl * 80 + kq * 16) = pk;
        uint32_t bb = sb + 1024 + s * EMBH_STAGE + 5120;
#pragma unroll
        for (int j = 0; j < 2; j++) {
            int id = t + j * 256, row = id >> 2, cc = id & 3;
            cp16(bb + row * 80 + cc * 16,
                 g_convw_h + (size_t)(e0 + row) * E + s * 32 + cc * 8, 16u);
        }
        CP_COMMIT();
    }

    int aRow = wp * 32 + (lane & 15);
    int aChi = lane >> 4;
    int bRow = wc * 32 + (lane >> 4) * 8 + (lane & 7);
    int bChi = (lane >> 3) & 1;

#pragma unroll 1
    for (int ch = 0; ch < 8; ch++) {
        CP_WAIT1();
        __syncthreads();
        bool pre = (ch + 2 < 8);
        int f = (ch + 2) % 3;
        float vp[8];
        if (pre) {
            // issue LDG early; cp.async B fill for chunk ch+2
#pragma unroll
            for (int j = 0; j < 8; j++)
                vp[j] = asrc[(size_t)((ch + 2) * 32 + kq * 8 + j) * HW];
            uint32_t bbn = sb + 1024 + f * EMBH_STAGE + 5120;
#pragma unroll
            for (int j = 0; j < 2; j++) {
                int id = t + j * 256, row = id >> 2, cc = id & 3;
                cp16(bbn + row * 80 + cc * 16,
                     g_convw_h + (size_t)(e0 + row) * E + (ch + 2) * 32 + cc * 8, 16u);
            }
        }
        CP_COMMIT();

        int s = ch % 3;
        uint32_t ab = sb + 1024 + s * EMBH_STAGE;
        uint32_t bb = ab + 5120;
#pragma unroll
        for (int kk = 0; kk < 2; kk++) {
            uint32_t a[2][4];
#pragma unroll
            for (int mt = 0; mt < 2; mt++)
                ldsm4(a[mt], ab + (aRow + mt * 16) * 80 + kk * 32 + aChi * 16);
            uint32_t bf[2][4];
#pragma unroll
            for (int g = 0; g < 2; g++)
                ldsm4(bf[g], bb + (bRow + g * 16) * 80 + kk * 32 + bChi * 16);
#pragma unroll
            for (int nt = 0; nt < 4; nt++) {
                uint32_t b0 = bf[nt >> 1][(nt & 1) * 2];
                uint32_t b1 = bf[nt >> 1][(nt & 1) * 2 + 1];
                mma_f16(c[0][nt], a[0][0], a[0][1], a[0][2], a[0][3], b0, b1);
                mma_f16(c[1][nt], a[1][0], a[1][1], a[1][2], a[1][3], b0, b1);
            }
        }

        if (pre) {   // STS of A for chunk ch+2 (guarded by future top-syncs)
            __half2 h0 = __floats2half2_rn(vp[0], vp[1]);
            __half2 h1 = __floats2half2_rn(vp[2], vp[3]);
            __half2 h2 = __floats2half2_rn(vp[4], vp[5]);
            __half2 h3 = __floats2half2_rn(vp[6], vp[7]);
            uint4 pk;
            pk.x = *(const uint32_t*)&h0; pk.y = *(const uint32_t*)&h1;
            pk.z = *(const uint32_t*)&h2; pk.w = *(const uint32_t*)&h3;
            *(uint4*)((char*)smem + 1024 + f * EMBH_STAGE + pixl * 80 + kq * 16) = pk;
        }
    }

    // Epilogue: bias, ssq atomics, direct fp16 store (unnormalized)
#pragma unroll
    for (int mt = 0; mt < 2; mt++) {
        int row = wp * 32 + mt * 16 + (lane >> 2);
        float s0 = 0.f, s1 = 0.f;
#pragma unroll
        for (int nt = 0; nt < 4; nt++) {
            int col = wc * 32 + nt * 8 + 2 * (lane & 3);
            float b0f = bias_sh[col], b1f = bias_sh[col + 1];
            c[mt][nt][0] += b0f; c[mt][nt][1] += b1f;
            c[mt][nt][2] += b0f; c[mt][nt][3] += b1f;
            s0 = fmaf(c[mt][nt][0], c[mt][nt][0], s0);
            s0 = fmaf(c[mt][nt][1], c[mt][nt][1], s0);
            s1 = fmaf(c[mt][nt][2], c[mt][nt][2], s1);
            s1 = fmaf(c[mt][nt][3], c[mt][nt][3], s1);
            __half2 h0 = __floats2half2_rn(c[mt][nt][0], c[mt][nt][1]);
            __half2 h1 = __floats2half2_rn(c[mt][nt][2], c[mt][nt][3]);
            *(__half2*)(g_emb_h + (size_t)(pix0 + row) * E + e0 + col) = h0;
            *(__half2*)(g_emb_h + (size_t)(pix0 + row + 8) * E + e0 + col) = h1;
        }
        atomicAdd(&ssq_sh[row], s0);
        atomicAdd(&ssq_sh[row + 8], s1);
    }
    __syncthreads();
    if (t < 64) atomicAdd(&g_ssq[pix0 + t], ssq_sh[t]);
}

// ---------------------------------------------------------------------------
// inv_ssq: g_inv = 1/max(sqrt(ssq), eps)
// ---------------------------------------------------------------------------
__global__ void inv_ssq() {
    int i = blockIdx.x * blockDim.x + threadIdx.x;
    if (i < NPIX) g_inv[i] = 1.f / fmaxf(sqrtf(g_ssq[i]), 1e-12f);
}

// ===========================================================================
// Kernel 3: main GEMM + epilogue (fp16 mma).  Block = 128 pix x 96 cols
// (32 r x 3 modes), K=256, 8 chunks of k=32, 4 stages, fill distance 3,
// SINGLE sync per chunk.
// smem: psum@0 (128f), inv@128 (128f), tiles@1024B: stage 17920B x4
//   Cs reuse @256f, stride 101 (51712B)
// ===========================================================================
#define MAIN_STAGE 17920
#define MAIN_SMEM  (1024 + 4 * MAIN_STAGE)   // 72704

__device__ __forceinline__ void main_fill(uint32_t sb, int t, int pix0, int r0,
                                          int s, int ch) {
    uint32_t ab = sb + 1024 + s * MAIN_STAGE;
    uint32_t bb = ab + 10240;
    int k0 = ch * 32;   // in halves
#pragma unroll
    for (int j = 0; j < 2; j++) {
        int id = t + j * 256, row = id >> 2, cc = id & 3;
        cp16(ab + row * 80 + cc * 16,
             g_emb_h + (size_t)(pix0 + row) * E + k0 + cc * 8, 16u);
    }
#pragma unroll
    for (int j = 0; j < 2; j++) {
        int id = t + j * 256;
        if (id < 384) {
            int row = id >> 2, cc = id & 3;
            int m = row >> 5, rl = row & 31, r = r0 + rl;
            const __half* src = g_brep_h;
            uint32_t sz = 0u;
            if (r < RR) {
                src = g_brep_h + (size_t)(m * RR + r) * E + k0 + cc * 8;
                sz = 16u;
            }
            cp16(bb + row * 80 + cc * 16, src, sz);
        }
    }
    CP_COMMIT();
}

__global__ __launch_bounds__(256, 3)
void main_tc(float* __restrict__ out) {
    extern __shared__ float smem[];
    float* psum_sh = smem;                 // 128
    float* inv_sh  = smem + 128;           // 128
    float* Cs      = smem + 256;           // reuse tiles, stride 101
    uint32_t sb = smem_u32(smem);
    int t = threadIdx.x, lane = t & 31, w = t >> 5;
    int wp = w & 3, wc = w >> 2;           // pix quarter, col half
    int pix0 = blockIdx.x * 128;
    int r0 = blockIdx.y * 32;

    if (t < 128) { psum_sh[t] = 0.f; inv_sh[t] = g_inv[pix0 + t]; }

    float c[2][6][4];
#pragma unroll
    for (int mt = 0; mt < 2; mt++)
#pragma unroll
        for (int nt = 0; nt < 6; nt++)
#pragma unroll
            for (int q = 0; q < 4; q++) c[mt][nt][q] = 0.f;

    main_fill(sb, t, pix0, r0, 0, 0);
    main_fill(sb, t, pix0, r0, 1, 1);
    main_fill(sb, t, pix0, r0, 2, 2);

    int aRow = wp * 32 + (lane & 15);
    int aChi = lane >> 4;
    int bRow = wc * 48 + (lane >> 4) * 8 + (lane & 7);
    int bChi = (lane >> 3) & 1;

#pragma unroll 1
    for (int ch = 0; ch < 8; ch++) {
        CP_WAIT2();
        __syncthreads();
        if (ch + 3 < 8) main_fill(sb, t, pix0, r0, (ch + 3) & 3, ch + 3);
        else CP_COMMIT();

        int s = ch & 3;
        uint32_t ab = sb + 1024 + s * MAIN_STAGE;
        uint32_t bb = ab + 10240;
#pragma unroll
        for (int kk = 0; kk < 2; kk++) {
            uint32_t a[2][4];
#pragma unroll
            for (int mt = 0; mt < 2; mt++)
                ldsm4(a[mt], ab + (aRow + mt * 16) * 80 + kk * 32 + aChi * 16);
            uint32_t bf[3][4];
#pragma unroll
            for (int g = 0; g < 3; g++)
                ldsm4(bf[g], bb + (bRow + g * 16) * 80 + kk * 32 + bChi * 16);
#pragma unroll
            for (int nt = 0; nt < 6; nt++) {
                uint32_t b0 = bf[nt >> 1][(nt & 1) * 2];
                uint32_t b1 = bf[nt >> 1][(nt & 1) * 2 + 1];
                mma_f16(c[0][nt], a[0][0], a[0][1], a[0][2], a[0][3], b0, b1);
                mma_f16(c[1][nt], a[1][0], a[1][1], a[1][2], a[1][3], b0, b1);
            }
        }
    }

    // stage C to smem (stride 101)
    __syncthreads();
#pragma unroll
    for (int mt = 0; mt < 2; mt++)
#pragma unroll
        for (int nt = 0; nt < 6; nt++) {
            int row = wp * 32 + mt * 16 + (lane >> 2);
            int col = wc * 48 + nt * 8 + 2 * (lane & 3);
            Cs[row * 101 + col]           = c[mt][nt][0];
            Cs[row * 101 + col + 1]       = c[mt][nt][1];
            Cs[(row + 8) * 101 + col]     = c[mt][nt][2];
            Cs[(row + 8) * 101 + col + 1] = c[mt][nt][3];
        }
    __syncthreads();

    // epilogue: pl = t&31 -> pixels pl+32i; rq = t>>5 -> rl = rq*4+jj
    int pl = t & 31, rq = t >> 5;
    float pacc[4] = {0.f, 0.f, 0.f, 0.f};
#pragma unroll
    for (int i = 0; i < 4; i++) {
        int p = pl + 32 * i;
        int gp = pix0 + p;
        int b = gp >> 12, hw = gp & 4095;
        float invp = inv_sh[p];
#pragma unroll
        for (int jj = 0; jj < 4; jj++) {
            int rl = rq * 4 + jj;
            int r = r0 + rl;
            if (r < RR) {
                float dot0 = Cs[p * 101 + rl] * invp;
                float dot1 = Cs[p * 101 + 32 + rl] * invp;
                float dot2 = Cs[p * 101 + 64 + rl] * invp;
                float d2 = fmaxf(2.f - 2.f * dot0, 0.f);
                float e1 = fmaxf(2.f - 2.f * dot1, 0.f);
                float e2 = fmaxf(2.f - 2.f * dot2, 0.f);
                float d   = sqrtf(d2);
                float dn1 = sqrtf(e1);
                float dn2 = sqrtf(e2);
                float mind2 = fminf(e1, e2);
                float dnmin = fminf(dn1, dn2);
                float clsneg = __expf(-2.f * mind2);
                float pori   = __expf(-2.f * d2);
                float tt = d + 0.3f * (2.f - dnmin);
                float pr = __expf(-2.f * tt * tt);
                unsigned base = ((unsigned)b * RR + r) * HW + hw;
                out[base]            = pr;       // cls_score (unnormalized)
                out[N1 + base]       = clsneg;   // cls_score_neg
                out[2u * N1 + base]  = d;        // distance
                unsigned dnb = ((unsigned)b * RR + r) * 2u * HW + hw;
                out[3u * N1 + dnb]      = dn1;   // distance_neg m=0
                out[3u * N1 + dnb + HW] = dn2;   // distance_neg m=1
                out[5u * N1 + base]  = pori;     // probs_ori
                pacc[i] += pr;
            }
        }
    }
#pragma unroll
    for (int i = 0; i < 4; i++) atomicAdd(&psum_sh[pl + 32 * i], pacc[i]);
    __syncthreads();
    if (t < 128) atomicAdd(&g_psum[pix0 + t], psum_sh[t]);
}

// ---------------------------------------------------------------------------
// Small kernels
// ---------------------------------------------------------------------------
__global__ void recip_psum() {
    int i = blockIdx.x * blockDim.x + threadIdx.x;
    if (i < NPIX) g_psum[i] = 1.f / g_psum[i];
}
__global__ void norm4(float* __restrict__ out) {
    unsigned i4 = blockIdx.x * blockDim.x + threadIdx.x;
    unsigned idx = i4 * 4u;
    if (idx < N1) {
        unsigned hw = idx & 4095u;
        unsigned br = idx >> 12;
        unsigned b = br / RR;
        float4 v = *(float4*)(out + idx);
        float4 s = *(const float4*)&g_psum[(b << 12) + hw];
        v.x *= s.x; v.y *= s.y; v.z *= s.z; v.w *= s.w;
        *(float4*)(out + idx) = v;
    }
}

// ---------------------------------------------------------------------------
extern "C" void kernel_launch(void* const* d_in, const int* in_sizes, int n_in,
                              void* d_out, int out_size) {
    (void)in_sizes; (void)n_in; (void)out_size;
    const float* x      = (const float*)d_in[0];
    const float* conv_w = (const float*)d_in[1];
    const float* conv_b = (const float*)d_in[2];
    const float* reps   = (const float*)d_in[3];
    const float* neg_w  = (const float*)d_in[4];
    const float* neg_b  = (const float*)d_in[5];
    float* out = (float*)d_out;

    cudaFuncSetAttribute(emb_f16, cudaFuncAttributeMaxDynamicSharedMemorySize, EMBH_SMEM);
    cudaFuncSetAttribute(main_tc, cudaFuncAttributeMaxDynamicSharedMemorySize, MAIN_SMEM);

    convert_inputs<<<(NCONV + NREPS + 255) / 256, 256>>>(conv_w, reps);
    negreps_kernel<<<dim3(RR, 2), 256>>>(reps, neg_w, neg_b);
    emb_f16<<<dim3(NPIX / 64, 2), 256, EMBH_SMEM>>>(x, conv_b);
    inv_ssq<<<NPIX / 256, 256>>>();
    main_tc<<<dim3(NPIX / 128, 12), 256, MAIN_SMEM>>>(out);
    recip_psum<<<NPIX / 256, 256>>>();
    norm4<<<(N1 / 4 + 255) / 256, 256>>>(out);
}

// round 14
// speedup vs baseline: 1.4471x; 1.4471x over previous
#include <cuda_runtime.h>
#include <cuda_fp16.h>
#include <cstdint>
#include <math.h>

#define HW 4096
#define NPIX 65536
#define E 256
#define RR 365
#define N1 23920640u

// Scratch (device globals; no runtime allocation allowed)
__device__ __align__(16) __half g_emb_h[NPIX * E];     // UNNORMALIZED conv out (fp16)
__device__ __align__(16) __half g_brep_h[3 * RR * E];  // [m][r][E] fp16 unit reps
__device__ __align__(16) __half g_convw_h[E * E];      // conv_w fp16 [e][cin]
__device__ float g_psum[NPIX];                         // per-pixel sum of probs over r
__device__ float g_ssq[NPIX];                          // per-pixel ||conv out||^2
__device__ float g_inv[NPIX];                          // 1/max(sqrt(ssq),eps)

// ---------------------------------------------------------------------------
// PTX helpers (sm_80+ baseline ISA; compiles for plain sm_103)
// ---------------------------------------------------------------------------
__device__ __forceinline__ uint32_t smem_u32(const void* p) {
    uint32_t a;
    asm("{ .reg .u64 t; cvta.to.shared.u64 t, %1; cvt.u32.u64 %0, t; }"
        : "=r"(a) : "l"(p));
    return a;
}

__device__ __forceinline__ void cp16(uint32_t dst, const void* src, uint32_t sz) {
    asm volatile("cp.async.cg.shared.global [%0], [%1], 16, %2;"
                 :: "r"(dst), "l"(src), "r"(sz));
}
#define CP_COMMIT() asm volatile("cp.async.commit_group;" ::: "memory")
#define CP_WAIT1()  asm volatile("cp.async.wait_group 1;" ::: "memory")
#define CP_WAIT3()  asm volatile("cp.async.wait_group 3;" ::: "memory")

__device__ __forceinline__ void ldsm4(uint32_t r[4], uint32_t addr) {
    asm volatile("ldmatrix.sync.aligned.m8n8.x4.shared.b16 {%0,%1,%2,%3}, [%4];"
                 : "=r"(r[0]), "=r"(r[1]), "=r"(r[2]), "=r"(r[3]) : "r"(addr));
}

// fp16 MMA, fp32 accumulate
__device__ __forceinline__ void mma_f16(float c[4],
                                        uint32_t a0, uint32_t a1, uint32_t a2, uint32_t a3,
                                        uint32_t b0, uint32_t b1) {
    asm volatile(
        "mma.sync.aligned.m16n8k16.row.col.f32.f16.f16.f32 "
        "{%0,%1,%2,%3}, {%4,%5,%6,%7}, {%8,%9}, {%0,%1,%2,%3};"
        : "+f"(c[0]), "+f"(c[1]), "+f"(c[2]), "+f"(c[3])
        : "r"(a0), "r"(a1), "r"(a2), "r"(a3), "r"(b0), "r"(b1));
}

// ---------------------------------------------------------------------------
// Kernel 0: convert conv_w + reps to fp16; zero psum/ssq
// ---------------------------------------------------------------------------
#define NCONV (E * E)
#define NREPS (RR * E)
__global__ void convert_inputs(const float* __restrict__ conv_w,
                               const float* __restrict__ reps) {
    int i = blockIdx.x * 256 + threadIdx.x;
    if (i < NCONV) g_convw_h[i] = __float2half(conv_w[i]);
    else if (i < NCONV + NREPS) g_brep_h[i - NCONV] = __float2half(reps[i - NCONV]);
    if (i < NPIX) { g_psum[i] = 0.f; g_ssq[i] = 0.f; }
}

// ---------------------------------------------------------------------------
// Kernel 1: negative representations -> g_brep_h rows RR..3RR-1 (fp16)
// ---------------------------------------------------------------------------
__global__ __launch_bounds__(256)
void negreps_kernel(const float* __restrict__ reps,
                    const float* __restrict__ neg_w,
                    const float* __restrict__ neg_b) {
    __shared__ __align__(16) float rs[E];
    __shared__ __align__(16) float Ws[16][E];
    __shared__ float red[256];
    int r = blockIdx.x, m = blockIdx.y;
    int t = threadIdx.x;

    rs[t] = reps[r * E + t];
    float off = neg_b[m * E + t];
    const float* wrow = neg_w + (size_t)(m * E + t) * E;

    for (int c0 = 0; c0 < E; c0 += 16) {
        __syncthreads();
        float4 v0 = *(const float4*)(wrow + c0);
        float4 v1 = *(const float4*)(wrow + c0 + 4);
        float4 v2 = *(const float4*)(wrow + c0 + 8);
        float4 v3 = *(const float4*)(wrow + c0 + 12);
        Ws[0][t]  = v0.x; Ws[1][t]  = v0.y; Ws[2][t]  = v0.z; Ws[3][t]  = v0.w;
        Ws[4][t]  = v1.x; Ws[5][t]  = v1.y; Ws[6][t]  = v1.z; Ws[7][t]  = v1.w;
        Ws[8][t]  = v2.x; Ws[9][t]  = v2.y; Ws[10][t] = v2.z; Ws[11][t] = v2.w;
        Ws[12][t] = v3.x; Ws[13][t] = v3.y; Ws[14][t] = v3.z; Ws[15][t] = v3.w;
        __syncthreads();
#pragma unroll
        for (int k = 0; k < 16; k++)
            off = fmaf(fabsf(rs[c0 + k]), Ws[k][t], off);
    }

    float xv = rs[t];
    float sg = (xv > 0.f) ? 1.f : ((xv < 0.f) ? -1.f : 0.f);
    float val = (off + fabsf(xv)) * sg;

    red[t] = val * val;
    __syncthreads();
    for (int s = 128; s > 0; s >>= 1) {
        if (t < s) red[t] += red[t + s];
        __syncthreads();
    }
    float invn = 1.f / fmaxf(sqrtf(red[0]), 1e-12f);
    g_brep_h[(size_t)((m + 1) * RR + r) * E + t] = __float2half(val * invn);
}

// ===========================================================================
// Kernel 2: conv1x1(x)+b, UNNORMALIZED, fp16 out; ssq accumulated globally.
// Block = 64 pix x 128 e (grid.y=2 e-halves). K=256, 8 chunks of k=32,
// 2-stage pipeline: LDG-prefetch transpose for A(x), cp.async for B(conv_w).
// smem: bias[128]@0, ssq_sh[64]@512B, tiles@1024B:
//   stage = A 64x80B (5120) + B 128x80B (10240) = 15360 x2
// ===========================================================================
#define EMBH_STAGE 15360
#define EMBH_SMEM  (1024 + 2 * EMBH_STAGE)   // 31744

__global__ __launch_bounds__(256, 3)
void emb_f16(const float* __restrict__ x, const float* __restrict__ conv_b) {
    extern __shared__ float smem[];
    float* bias_sh = smem;          // 128
    float* ssq_sh  = smem + 128;    // 64
    uint32_t sb = smem_u32(smem);
    int t = threadIdx.x, lane = t & 31, w = t >> 5;
    int wp = w & 1, wc = w >> 1;    // 32-pix half, 32-e quarter
    int pix0 = blockIdx.x * 64;
    int e0 = blockIdx.y * 128;
    int b = pix0 >> 12, hw0 = pix0 & 4095;

    if (t < 128) bias_sh[t] = conv_b[e0 + t];
    if (t < 64) ssq_sh[t] = 0.f;
    __syncthreads();

    float c[2][4][4];
#pragma unroll
    for (int mt = 0; mt < 2; mt++)
#pragma unroll
        for (int nt = 0; nt < 4; nt++)
#pragma unroll
            for (int q = 0; q < 4; q++) c[mt][nt][q] = 0.f;

    int pixl = t & 63, kq = t >> 6;     // kq: 0..3 (8 k each)
    const float* asrc = x + (size_t)b * E * HW + hw0 + pixl;

    // ---- fill helpers ----
    float v0[8], v1[8];
#pragma unroll
    for (int j = 0; j < 8; j++) v0[j] = asrc[(size_t)(0 * 32 + kq * 8 + j) * HW];
#pragma unroll
    for (int j = 0; j < 8; j++) v1[j] = asrc[(size_t)(1 * 32 + kq * 8 + j) * HW];

#pragma unroll
    for (int s = 0; s < 2; s++) {
        float* v = (s == 0) ? v0 : v1;
        __half2 h0 = __floats2half2_rn(v[0], v[1]);
        __half2 h1 = __floats2half2_rn(v[2], v[3]);
        __half2 h2 = __floats2half2_rn(v[4], v[5]);
        __half2 h3 = __floats2half2_rn(v[6], v[7]);
        uint4 pk;
        pk.x = *(const uint32_t*)&h0; pk.y = *(const uint32_t*)&h1;
        pk.z = *(const uint32_t*)&h2; pk.w = *(const uint32_t*)&h3;
        *(uint4*)((char*)smem + 1024 + s * EMBH_STAGE + pixl * 80 + kq * 16) = pk;
        uint32_t bb = sb + 1024 + s * EMBH_STAGE + 5120;
#pragma unroll
        for (int j = 0; j < 2; j++) {
            int id = t + j * 256, row = id >> 2, cc = id & 3;
            cp16(bb + row * 80 + cc * 16,
                 g_convw_h + (size_t)(e0 + row) * E + s * 32 + cc * 8, 16u);
        }
        CP_COMMIT();
    }

    int aRow = wp * 32 + (lane & 15);
    int aChi = lane >> 4;
    int bRow = wc * 32 + (lane >> 4) * 8 + (lane & 7);
    int bChi = (lane >> 3) & 1;

#pragma unroll 1
    for (int ch = 0; ch < 8; ch++) {
        CP_WAIT1();
        __syncthreads();
        bool pre = (ch + 2 < 8);
        float vp[8];
        if (pre) {
#pragma unroll
            for (int j = 0; j < 8; j++)
                vp[j] = asrc[(size_t)((ch + 2) * 32 + kq * 8 + j) * HW];
        }
        int s = ch & 1;
        uint32_t ab = sb + 1024 + s * EMBH_STAGE;
        uint32_t bb = ab + 5120;
#pragma unroll
        for (int kk = 0; kk < 2; kk++) {
            uint32_t a[2][4];
#pragma unroll
            for (int mt = 0; mt < 2; mt++)
                ldsm4(a[mt], ab + (aRow + mt * 16) * 80 + kk * 32 + aChi * 16);
            uint32_t bf[2][4];
#pragma unroll
            for (int g = 0; g < 2; g++)
                ldsm4(bf[g], bb + (bRow + g * 16) * 80 + kk * 32 + bChi * 16);
#pragma unroll
            for (int nt = 0; nt < 4; nt++) {
                uint32_t b0 = bf[nt >> 1][(nt & 1) * 2];
                uint32_t b1 = bf[nt >> 1][(nt & 1) * 2 + 1];
                mma_f16(c[0][nt], a[0][0], a[0][1], a[0][2], a[0][3], b0, b1);
                mma_f16(c[1][nt], a[1][0], a[1][1], a[1][2], a[1][3], b0, b1);
            }
        }
        __syncthreads();
        if (pre) {
            __half2 h0 = __floats2half2_rn(vp[0], vp[1]);
            __half2 h1 = __floats2half2_rn(vp[2], vp[3]);
            __half2 h2 = __floats2half2_rn(vp[4], vp[5]);
            __half2 h3 = __floats2half2_rn(vp[6], vp[7]);
            uint4 pk;
            pk.x = *(const uint32_t*)&h0; pk.y = *(const uint32_t*)&h1;
            pk.z = *(const uint32_t*)&h2; pk.w = *(const uint32_t*)&h3;
            *(uint4*)((char*)smem + 1024 + s * EMBH_STAGE + pixl * 80 + kq * 16) = pk;
            uint32_t bbn = sb + 1024 + s * EMBH_STAGE + 5120;
#pragma unroll
            for (int j = 0; j < 2; j++) {
                int id = t + j * 256, row = id >> 2, cc = id & 3;
                cp16(bbn + row * 80 + cc * 16,
                     g_convw_h + (size_t)(e0 + row) * E + (ch + 2) * 32 + cc * 8, 16u);
            }
            CP_COMMIT();
        } else {
            CP_COMMIT();
        }
    }

    // Epilogue: bias, ssq atomics, direct fp16 store (unnormalized)
#pragma unroll
    for (int mt = 0; mt < 2; mt++) {
        int row = wp * 32 + mt * 16 + (lane >> 2);
        float s0 = 0.f, s1 = 0.f;
#pragma unroll
        for (int nt = 0; nt < 4; nt++) {
            int col = wc * 32 + nt * 8 + 2 * (lane & 3);
            float b0f = bias_sh[col], b1f = bias_sh[col + 1];
            c[mt][nt][0] += b0f; c[mt][nt][1] += b1f;
            c[mt][nt][2] += b0f; c[mt][nt][3] += b1f;
            s0 = fmaf(c[mt][nt][0], c[mt][nt][0], s0);
            s0 = fmaf(c[mt][nt][1], c[mt][nt][1], s0);
            s1 = fmaf(c[mt][nt][2], c[mt][nt][2], s1);
            s1 = fmaf(c[mt][nt][3], c[mt][nt][3], s1);
            __half2 h0 = __floats2half2_rn(c[mt][nt][0], c[mt][nt][1]);
            __half2 h1 = __floats2half2_rn(c[mt][nt][2], c[mt][nt][3]);
            *(__half2*)(g_emb_h + (size_t)(pix0 + row) * E + e0 + col) = h0;
            *(__half2*)(g_emb_h + (size_t)(pix0 + row + 8) * E + e0 + col) = h1;
        }
        atomicAdd(&ssq_sh[row], s0);
        atomicAdd(&ssq_sh[row + 8], s1);
    }
    __syncthreads();
    if (t < 64) atomicAdd(&g_ssq[pix0 + t], ssq_sh[t]);
}

// ---------------------------------------------------------------------------
// inv_ssq: g_inv = 1/max(sqrt(ssq), eps)
// ---------------------------------------------------------------------------
__global__ void inv_ssq() {
    int i = blockIdx.x * blockDim.x + threadIdx.x;
    if (i < NPIX) g_inv[i] = 1.f / fmaxf(sqrtf(g_ssq[i]), 1e-12f);
}

// ===========================================================================
// Kernel 3: main GEMM + epilogue (fp16 mma).  Block = 128 pix x 96 cols
// (32 r x 3 modes), K=256, 8 chunks of k=32, 4-stage cp.async, fill at
// bottom (distance 4), two syncs per chunk — R12 proven structure.
// smem: psum@0 (128f), inv@128 (128f), tiles@1024B: stage 17920B x4
//   Cs reuse @256f, stride 101 (51712B)
// ===========================================================================
#define MAIN_STAGE 17920
#define MAIN_SMEM  (1024 + 4 * MAIN_STAGE)   // 72704

__device__ __forceinline__ void main_fill(uint32_t sb, int t, int pix0, int r0,
                                          int s, int ch) {
    uint32_t ab = sb + 1024 + s * MAIN_STAGE;
    uint32_t bb = ab + 10240;
    int k0 = ch * 32;   // in halves
#pragma unroll
    for (int j = 0; j < 2; j++) {
        int id = t + j * 256, row = id >> 2, cc = id & 3;
        cp16(ab + row * 80 + cc * 16,
             g_emb_h + (size_t)(pix0 + row) * E + k0 + cc * 8, 16u);
    }
#pragma unroll
    for (int j = 0; j < 2; j++) {
        int id = t + j * 256;
        if (id < 384) {
            int row = id >> 2, cc = id & 3;
            int m = row >> 5, rl = row & 31, r = r0 + rl;
            const __half* src = g_brep_h;
            uint32_t sz = 0u;
            if (r < RR) {
                src = g_brep_h + (size_t)(m * RR + r) * E + k0 + cc * 8;
                sz = 16u;
            }
            cp16(bb + row * 80 + cc * 16, src, sz);
        }
    }
    CP_COMMIT();
}

__global__ __launch_bounds__(256, 3)
void main_tc(float* __restrict__ out) {
    extern __shared__ float smem[];
    float* psum_sh = smem;                 // 128
    float* inv_sh  = smem + 128;           // 128
    float* Cs      = smem + 256;           // reuse tiles, stride 101
    uint32_t sb = smem_u32(smem);
    int t = threadIdx.x, lane = t & 31, w = t >> 5;
    int wp = w & 3, wc = w >> 2;           // pix quarter, col half
    int pix0 = blockIdx.x * 128;
    int r0 = blockIdx.y * 32;

    if (t < 128) { psum_sh[t] = 0.f; inv_sh[t] = g_inv[pix0 + t]; }

    float c[2][6][4];
#pragma unroll
    for (int mt = 0; mt < 2; mt++)
#pragma unroll
        for (int nt = 0; nt < 6; nt++)
#pragma unroll
            for (int q = 0; q < 4; q++) c[mt][nt][q] = 0.f;

    main_fill(sb, t, pix0, r0, 0, 0);
    main_fill(sb, t, pix0, r0, 1, 1);
    main_fill(sb, t, pix0, r0, 2, 2);
    main_fill(sb, t, pix0, r0, 3, 3);

    int aRow = wp * 32 + (lane & 15);
    int aChi = lane >> 4;
    int bRow = wc * 48 + (lane >> 4) * 8 + (lane & 7);
    int bChi = (lane >> 3) & 1;

#pragma unroll 1
    for (int ch = 0; ch < 8; ch++) {
        CP_WAIT3();
        __syncthreads();
        int s = ch & 3;
        uint32_t ab = sb + 1024 + s * MAIN_STAGE;
        uint32_t bb = ab + 10240;
#pragma unroll
        for (int kk = 0; kk < 2; kk++) {
            uint32_t a[2][4];
#pragma unroll
            for (int mt = 0; mt < 2; mt++)
                ldsm4(a[mt], ab + (aRow + mt * 16) * 80 + kk * 32 + aChi * 16);
            uint32_t bf[3][4];
#pragma unroll
            for (int g = 0; g < 3; g++)
                ldsm4(bf[g], bb + (bRow + g * 16) * 80 + kk * 32 + bChi * 16);
#pragma unroll
            for (int nt = 0; nt < 6; nt++) {
                uint32_t b0 = bf[nt >> 1][(nt & 1) * 2];
                uint32_t b1 = bf[nt >> 1][(nt & 1) * 2 + 1];
                mma_f16(c[0][nt], a[0][0], a[0][1], a[0][2], a[0][3], b0, b1);
                mma_f16(c[1][nt], a[1][0], a[1][1], a[1][2], a[1][3], b0, b1);
            }
        }
        __syncthreads();
        if (ch + 4 < 8) main_fill(sb, t, pix0, r0, s, ch + 4);
        else CP_COMMIT();
    }

    // stage C to smem (stride 101)
#pragma unroll
    for (int mt = 0; mt < 2; mt++)
#pragma unroll
        for (int nt = 0; nt < 6; nt++) {
            int row = wp * 32 + mt * 16 + (lane >> 2);
            int col = wc * 48 + nt * 8 + 2 * (lane & 3);
            Cs[row * 101 + col]           = c[mt][nt][0];
            Cs[row * 101 + col + 1]       = c[mt][nt][1];
            Cs[(row + 8) * 101 + col]     = c[mt][nt][2];
            Cs[(row + 8) * 101 + col + 1] = c[mt][nt][3];
        }
    __syncthreads();

    // epilogue: pl = t&31 -> pixels pl+32i; rq = t>>5 -> rl = rq*4+jj
    int pl = t & 31, rq = t >> 5;
    float pacc[4] = {0.f, 0.f, 0.f, 0.f};
#pragma unroll
    for (int i = 0; i < 4; i++) {
        int p = pl + 32 * i;
        int gp = pix0 + p;
        int b = gp >> 12, hw = gp & 4095;
        float invp = inv_sh[p];
#pragma unroll
        for (int jj = 0; jj < 4; jj++) {
            int rl = rq * 4 + jj;
            int r = r0 + rl;
            if (r < RR) {
                float dot0 = Cs[p * 101 + rl] * invp;
                float dot1 = Cs[p * 101 + 32 + rl] * invp;
                float dot2 = Cs[p * 101 + 64 + rl] * invp;
                float d2 = fmaxf(2.f - 2.f * dot0, 0.f);
                float e1 = fmaxf(2.f - 2.f * dot1, 0.f);
                float e2 = fmaxf(2.f - 2.f * dot2, 0.f);
                float d   = sqrtf(d2);
                float dn1 = sqrtf(e1);
                float dn2 = sqrtf(e2);
                float mind2 = fminf(e1, e2);
                float dnmin = fminf(dn1, dn2);
                float clsneg = __expf(-2.f * mind2);
                float pori   = __expf(-2.f * d2);
                float tt = d + 0.3f * (2.f - dnmin);
                float pr = __expf(-2.f * tt * tt);
                unsigned base = ((unsigned)b * RR + r) * HW + hw;
                out[base]            = pr;       // cls_score (unnormalized)
                out[N1 + base]       = clsneg;   // cls_score_neg
                out[2u * N1 + base]  = d;        // distance
                unsigned dnb = ((unsigned)b * RR + r) * 2u * HW + hw;
                out[3u * N1 + dnb]      = dn1;   // distance_neg m=0
                out[3u * N1 + dnb + HW] = dn2;   // distance_neg m=1
                out[5u * N1 + base]  = pori;     // probs_ori
                pacc[i] += pr;
            }
        }
    }
#pragma unroll
    for (int i = 0; i < 4; i++) atomicAdd(&psum_sh[pl + 32 * i], pacc[i]);
    __syncthreads();
    if (t < 128) atomicAdd(&g_psum[pix0 + t], psum_sh[t]);
}

// ---------------------------------------------------------------------------
// Small kernels
// ---------------------------------------------------------------------------
__global__ void recip_psum() {
    int i = blockIdx.x * blockDim.x + threadIdx.x;
    if (i < NPIX) g_psum[i] = 1.f / g_psum[i];
}
__global__ void norm4(float* __restrict__ out) {
    unsigned i4 = blockIdx.x * blockDim.x + threadIdx.x;
    unsigned idx = i4 * 4u;
    if (idx < N1) {
        unsigned hw = idx & 4095u;
        unsigned br = idx >> 12;
        unsigned b = br / RR;
        float4 v = *(float4*)(out + idx);
        float4 s = *(const float4*)&g_psum[(b << 12) + hw];
        v.x *= s.x; v.y *= s.y; v.z *= s.z; v.w *= s.w;
        *(float4*)(out + idx) = v;
    }
}

// ---------------------------------------------------------------------------
extern "C" void kernel_launch(void* const* d_in, const int* in_sizes, int n_in,
                              void* d_out, int out_size) {
    (void)in_sizes; (void)n_in; (void)out_size;
    const float* x      = (const float*)d_in[0];
    const float* conv_w = (const float*)d_in[1];
    const float* conv_b = (const float*)d_in[2];
    const float* reps   = (const float*)d_in[3];
    const float* neg_w  = (const float*)d_in[4];
    const float* neg_b  = (const float*)d_in[5];
    float* out = (float*)d_out;

    cudaFuncSetAttribute(emb_f16, cudaFuncAttributeMaxDynamicSharedMemorySize, EMBH_SMEM);
    cudaFuncSetAttribute(main_tc, cudaFuncAttributeMaxDynamicSharedMemorySize, MAIN_SMEM);

    convert_inputs<<<(NCONV + NREPS + 255) / 256, 256>>>(conv_w, reps);
    negreps_kernel<<<dim3(RR, 2), 256>>>(reps, neg_w, neg_b);
    emb_f16<<<dim3(NPIX / 64, 2), 256, EMBH_SMEM>>>(x, conv_b);
    inv_ssq<<<NPIX / 256, 256>>>();
    main_tc<<<dim3(NPIX / 128, 12), 256, MAIN_SMEM>>>(out);
    recip_psum<<<NPIX / 256, 256>>>();
    norm4<<<(N1 / 4 + 255) / 256, 256>>>(out);
}